// round 2
// baseline (speedup 1.0000x reference)
#include <cuda_runtime.h>
#include <float.h>

#define Q     1024
#define D     512
#define NDATA 50000
#define NPAD  50048   // 391 * 128

// Scratch (allocation-free rule: __device__ globals)
__device__ float g_scores[(size_t)Q * NPAD];
__device__ float g_d2[NPAD];
__device__ int   g_t_is_i64;   // 1 if targets buffer is int64, 0 if int32

// ---------------------------------------------------------------------------
// Kernel 0: detect targets dtype. If the buffer is int64 (values in [0,100)),
// its int32 view has every odd word == 0. Any nonzero odd word => int32.
// ---------------------------------------------------------------------------
__global__ __launch_bounds__(256) void detect_dtype_kernel(const int* __restrict__ t32) {
    __shared__ int any_nz;
    if (threadIdx.x == 0) any_nz = 0;
    __syncthreads();
    int local = 0;
    for (int i = threadIdx.x; i < NDATA; i += 256)
        local |= t32[2 * i + 1];
    if (local) atomicOr(&any_nz, 1);
    __syncthreads();
    if (threadIdx.x == 0) g_t_is_i64 = (any_nz == 0) ? 1 : 0;
}

// ---------------------------------------------------------------------------
// Kernel 1: per-row squared norms of data (one warp per row, coalesced float4)
// ---------------------------------------------------------------------------
__global__ __launch_bounds__(256) void row_norms_kernel(const float* __restrict__ data) {
    int gw   = (blockIdx.x * blockDim.x + threadIdx.x) >> 5;
    int lane = threadIdx.x & 31;
    if (gw >= NDATA) return;
    const float4* row = reinterpret_cast<const float4*>(data + (size_t)gw * D);
    float s = 0.f;
#pragma unroll
    for (int j = 0; j < 4; ++j) {
        float4 v = row[lane + 32 * j];
        s += v.x * v.x + v.y * v.y + v.z * v.z + v.w * v.w;
    }
#pragma unroll
    for (int off = 16; off > 0; off >>= 1) s += __shfl_down_sync(0xffffffffu, s, off);
    if (lane == 0) g_d2[gw] = s;
}

// ---------------------------------------------------------------------------
// Kernel 2: score GEMM.  score[q][j] = ||d_j||^2 - 2 * <X_q, data_j>
// Ranking-equivalent to the reference distance (drops x^2 + sqrt, both
// monotone per query).  Classic SGEMM: BM=BN=128, BK=16, 8x8 per thread.
// ---------------------------------------------------------------------------
#define BM 128
#define BN 128
#define BK 16
#define TM 8
#define TN 8

__global__ __launch_bounds__(256) void score_gemm_kernel(const float* __restrict__ X,
                                                         const float* __restrict__ data) {
    __shared__ float As[BK][BM + 4];
    __shared__ float Bs[BK][BN + 4];

    const int tid  = threadIdx.x;
    const int tx   = tid & 15;   // 16 thread cols
    const int ty   = tid >> 4;   // 16 thread rows
    const int row0 = blockIdx.y * BM;
    const int col0 = blockIdx.x * BN;

    float acc[TM][TN];
#pragma unroll
    for (int i = 0; i < TM; ++i)
#pragma unroll
        for (int j = 0; j < TN; ++j) acc[i][j] = 0.f;

    for (int k0 = 0; k0 < D; k0 += BK) {
        // A tile: 128x16 floats = 512 float4, 2 per thread, stored transposed
#pragma unroll
        for (int l = 0; l < 2; ++l) {
            int vec = tid + l * 256;
            int r = vec >> 2, c4 = vec & 3;
            float4 v = *reinterpret_cast<const float4*>(X + (size_t)(row0 + r) * D + k0 + c4 * 4);
            As[c4 * 4 + 0][r] = v.x;
            As[c4 * 4 + 1][r] = v.y;
            As[c4 * 4 + 2][r] = v.z;
            As[c4 * 4 + 3][r] = v.w;
        }
        // B tile: rows of `data` (candidates), guarded at N boundary
#pragma unroll
        for (int l = 0; l < 2; ++l) {
            int vec = tid + l * 256;
            int r = vec >> 2, c4 = vec & 3;
            int gr = col0 + r;
            float4 v = make_float4(0.f, 0.f, 0.f, 0.f);
            if (gr < NDATA)
                v = *reinterpret_cast<const float4*>(data + (size_t)gr * D + k0 + c4 * 4);
            Bs[c4 * 4 + 0][r] = v.x;
            Bs[c4 * 4 + 1][r] = v.y;
            Bs[c4 * 4 + 2][r] = v.z;
            Bs[c4 * 4 + 3][r] = v.w;
        }
        __syncthreads();

#pragma unroll
        for (int kk = 0; kk < BK; ++kk) {
            float a[TM], b[TN];
            *reinterpret_cast<float4*>(&a[0]) = *reinterpret_cast<const float4*>(&As[kk][ty * TM]);
            *reinterpret_cast<float4*>(&a[4]) = *reinterpret_cast<const float4*>(&As[kk][ty * TM + 4]);
            *reinterpret_cast<float4*>(&b[0]) = *reinterpret_cast<const float4*>(&Bs[kk][tx * TN]);
            *reinterpret_cast<float4*>(&b[4]) = *reinterpret_cast<const float4*>(&Bs[kk][tx * TN + 4]);
#pragma unroll
            for (int i = 0; i < TM; ++i)
#pragma unroll
                for (int j = 0; j < TN; ++j)
                    acc[i][j] = fmaf(a[i], b[j], acc[i][j]);
        }
        __syncthreads();
    }

    // Epilogue: fold ||d||^2, store score
    float d2c[TN];
#pragma unroll
    for (int j = 0; j < TN; ++j) d2c[j] = g_d2[col0 + tx * TN + j];
#pragma unroll
    for (int i = 0; i < TM; ++i) {
        size_t base = (size_t)(row0 + ty * TM + i) * NPAD + col0 + tx * TN;
#pragma unroll
        for (int j = 0; j < TN; ++j)
            g_scores[base + j] = fmaf(-2.f, acc[i][j], d2c[j]);
    }
}

// ---------------------------------------------------------------------------
// Kernel 3: per-query exact top-10 (lexicographic (value,index) order -> same
// tie handling as jax top_k) + mode with smallest-label tie-break.
// One block (256 threads) per query.
// ---------------------------------------------------------------------------
__global__ __launch_bounds__(256) void topk_mode_kernel(const int* __restrict__ t32,
                                                        float* __restrict__ out) {
    const int q   = blockIdx.x;
    const int tid = threadIdx.x;
    const float* row = g_scores + (size_t)q * NPAD;

    float val[10];
    int   idx[10];
#pragma unroll
    for (int i = 0; i < 10; ++i) { val[i] = FLT_MAX; idx[i] = 0x7fffffff; }

    // Local top-10.  j increases monotonically, so equal values never replace
    // (keeps lower index — matches reference tie-break).
    for (int j = tid; j < NDATA; j += 256) {
        float v = row[j];
        if (v < val[9]) {
            int p = 9;
            while (p > 0 && v < val[p - 1]) {
                val[p] = val[p - 1]; idx[p] = idx[p - 1]; --p;
            }
            val[p] = v; idx[p] = j;
        }
    }

    __shared__ float sval[256 * 10];
    __shared__ int   sidx[256 * 10];
    __shared__ float rv[256];
    __shared__ int   ri[256];
    __shared__ int   rp[256];
    __shared__ int   winners[10];

#pragma unroll
    for (int i = 0; i < 10; ++i) { sval[tid * 10 + i] = val[i]; sidx[tid * 10 + i] = idx[i]; }
    __syncthreads();

    // 10 rounds of global argmin with (value, index) tie-break
    for (int round = 0; round < 10; ++round) {
        float bv = FLT_MAX; int bi = 0x7fffffff; int bp = -1;
#pragma unroll
        for (int t = 0; t < 10; ++t) {
            int p = tid * 10 + t;
            float v = sval[p]; int ix = sidx[p];
            if (v < bv || (v == bv && ix < bi)) { bv = v; bi = ix; bp = p; }
        }
        rv[tid] = bv; ri[tid] = bi; rp[tid] = bp;
        __syncthreads();
        for (int s = 128; s > 0; s >>= 1) {
            if (tid < s) {
                float v2 = rv[tid + s]; int i2 = ri[tid + s];
                if (v2 < rv[tid] || (v2 == rv[tid] && i2 < ri[tid])) {
                    rv[tid] = v2; ri[tid] = i2; rp[tid] = rp[tid + s];
                }
            }
            __syncthreads();
        }
        if (tid == 0) {
            winners[round] = ri[0];
            sval[rp[0]] = FLT_MAX;
            sidx[rp[0]] = 0x7fffffff;
        }
        __syncthreads();
    }

    if (tid == 0) {
        const int is64 = g_t_is_i64;
        int lab[10];
#pragma unroll
        for (int i = 0; i < 10; ++i) {
            int w = winners[i];
            lab[i] = is64 ? t32[2 * w] : t32[w];
        }
        int bestLab = 0x7fffffff, bestCnt = 0;
#pragma unroll
        for (int i = 0; i < 10; ++i) {
            int c = 0;
#pragma unroll
            for (int j2 = 0; j2 < 10; ++j2) c += (lab[j2] == lab[i]) ? 1 : 0;
            if (c > bestCnt || (c == bestCnt && lab[i] < bestLab)) { bestCnt = c; bestLab = lab[i]; }
        }
        out[q] = (float)bestLab;
    }
}

// ---------------------------------------------------------------------------
extern "C" void kernel_launch(void* const* d_in, const int* in_sizes, int n_in,
                              void* d_out, int out_size) {
    // Bind inputs by element count (robust to metadata ordering):
    //   X: 1024*512 = 524288,  data: 50000*512 = 25600000,  targets: 50000
    const float* X       = nullptr;
    const float* data    = nullptr;
    const int*   t32     = nullptr;
    for (int i = 0; i < n_in; ++i) {
        if (in_sizes[i] == Q * D)            X    = (const float*)d_in[i];
        else if (in_sizes[i] == NDATA * D)   data = (const float*)d_in[i];
        else if (in_sizes[i] == NDATA)       t32  = (const int*)d_in[i];
    }
    float* out = (float*)d_out;
    (void)out_size;

    detect_dtype_kernel<<<1, 256>>>(t32);
    row_norms_kernel<<<(NDATA * 32 + 255) / 256, 256>>>(data);

    dim3 grid(NPAD / BN, Q / BM);   // 391 x 8
    score_gemm_kernel<<<grid, 256>>>(X, data);

    topk_mode_kernel<<<Q, 256>>>(t32, out);
}

// round 3
// speedup vs baseline: 1.1247x; 1.1247x over previous
#include <cuda_runtime.h>
#include <float.h>

#define Q     1024
#define D     512
#define NDATA 50000
#define NPAD  50048   // 391 * 128

// Scratch (allocation-free rule: __device__ globals)
__device__ float g_scores[(size_t)Q * NPAD];
__device__ float g_d2[NPAD];
__device__ int   g_t_is_i64;   // 1 if targets buffer is int64, 0 if int32

// ---------------------------------------------------------------------------
// Kernel 0: detect targets dtype. If the buffer is int64 (values in [0,100)),
// its int32 view has every odd word == 0. Any nonzero odd word => int32.
// ---------------------------------------------------------------------------
__global__ __launch_bounds__(256) void detect_dtype_kernel(const int* __restrict__ t32) {
    __shared__ int any_nz;
    if (threadIdx.x == 0) any_nz = 0;
    __syncthreads();
    int local = 0;
    for (int i = threadIdx.x; i < NDATA; i += 256)
        local |= t32[2 * i + 1];
    if (local) atomicOr(&any_nz, 1);
    __syncthreads();
    if (threadIdx.x == 0) g_t_is_i64 = (any_nz == 0) ? 1 : 0;
}

// ---------------------------------------------------------------------------
// Kernel 1: per-row squared norms of data (one warp per row, coalesced float4)
// ---------------------------------------------------------------------------
__global__ __launch_bounds__(256) void row_norms_kernel(const float* __restrict__ data) {
    int gw   = (blockIdx.x * blockDim.x + threadIdx.x) >> 5;
    int lane = threadIdx.x & 31;
    if (gw >= NDATA) return;
    const float4* row = reinterpret_cast<const float4*>(data + (size_t)gw * D);
    float s = 0.f;
#pragma unroll
    for (int j = 0; j < 4; ++j) {
        float4 v = row[lane + 32 * j];
        s += v.x * v.x + v.y * v.y + v.z * v.z + v.w * v.w;
    }
#pragma unroll
    for (int off = 16; off > 0; off >>= 1) s += __shfl_down_sync(0xffffffffu, s, off);
    if (lane == 0) g_d2[gw] = s;
}

// ---------------------------------------------------------------------------
// Kernel 2: score GEMM with register-prefetch software pipelining.
// score[q][j] = ||d_j||^2 - 2 * <X_q, data_j>   (ranking-equivalent to dist)
// ---------------------------------------------------------------------------
#define BM 128
#define BN 128
#define BK 16
#define TM 8
#define TN 8

__global__ __launch_bounds__(256) void score_gemm_kernel(const float* __restrict__ X,
                                                         const float* __restrict__ data) {
    __shared__ float As[BK][BM + 4];
    __shared__ float Bs[BK][BN + 4];

    const int tid  = threadIdx.x;
    const int tx   = tid & 15;   // 16 thread cols
    const int ty   = tid >> 4;   // 16 thread rows
    const int row0 = blockIdx.y * BM;
    const int col0 = blockIdx.x * BN;

    // Per-thread load coordinates (2 float4 each for A and B)
    const int vec0 = tid;          // first vector id
    const int vec1 = tid + 256;    // second vector id
    const int ar0 = vec0 >> 2, ac0 = vec0 & 3;
    const int ar1 = vec1 >> 2, ac1 = vec1 & 3;

    float4 pa0, pa1, pb0, pb1;

    auto load_tiles = [&](int k0) {
        pa0 = *reinterpret_cast<const float4*>(X + (size_t)(row0 + ar0) * D + k0 + ac0 * 4);
        pa1 = *reinterpret_cast<const float4*>(X + (size_t)(row0 + ar1) * D + k0 + ac1 * 4);
        int g0 = col0 + ar0, g1 = col0 + ar1;
        pb0 = make_float4(0.f, 0.f, 0.f, 0.f);
        pb1 = make_float4(0.f, 0.f, 0.f, 0.f);
        if (g0 < NDATA) pb0 = *reinterpret_cast<const float4*>(data + (size_t)g0 * D + k0 + ac0 * 4);
        if (g1 < NDATA) pb1 = *reinterpret_cast<const float4*>(data + (size_t)g1 * D + k0 + ac1 * 4);
    };
    auto store_tiles = [&]() {
        As[ac0 * 4 + 0][ar0] = pa0.x; As[ac0 * 4 + 1][ar0] = pa0.y;
        As[ac0 * 4 + 2][ar0] = pa0.z; As[ac0 * 4 + 3][ar0] = pa0.w;
        As[ac1 * 4 + 0][ar1] = pa1.x; As[ac1 * 4 + 1][ar1] = pa1.y;
        As[ac1 * 4 + 2][ar1] = pa1.z; As[ac1 * 4 + 3][ar1] = pa1.w;
        Bs[ac0 * 4 + 0][ar0] = pb0.x; Bs[ac0 * 4 + 1][ar0] = pb0.y;
        Bs[ac0 * 4 + 2][ar0] = pb0.z; Bs[ac0 * 4 + 3][ar0] = pb0.w;
        Bs[ac1 * 4 + 0][ar1] = pb1.x; Bs[ac1 * 4 + 1][ar1] = pb1.y;
        Bs[ac1 * 4 + 2][ar1] = pb1.z; Bs[ac1 * 4 + 3][ar1] = pb1.w;
    };

    float acc[TM][TN];
#pragma unroll
    for (int i = 0; i < TM; ++i)
#pragma unroll
        for (int j = 0; j < TN; ++j) acc[i][j] = 0.f;

    load_tiles(0);
    store_tiles();
    __syncthreads();

    for (int k0 = 0; k0 < D; k0 += BK) {
        const bool has_next = (k0 + BK < D);
        if (has_next) load_tiles(k0 + BK);   // overlap with compute below

#pragma unroll
        for (int kk = 0; kk < BK; ++kk) {
            float a[TM], b[TN];
            *reinterpret_cast<float4*>(&a[0]) = *reinterpret_cast<const float4*>(&As[kk][ty * TM]);
            *reinterpret_cast<float4*>(&a[4]) = *reinterpret_cast<const float4*>(&As[kk][ty * TM + 4]);
            *reinterpret_cast<float4*>(&b[0]) = *reinterpret_cast<const float4*>(&Bs[kk][tx * TN]);
            *reinterpret_cast<float4*>(&b[4]) = *reinterpret_cast<const float4*>(&Bs[kk][tx * TN + 4]);
#pragma unroll
            for (int i = 0; i < TM; ++i)
#pragma unroll
                for (int j = 0; j < TN; ++j)
                    acc[i][j] = fmaf(a[i], b[j], acc[i][j]);
        }
        __syncthreads();
        if (has_next) {
            store_tiles();
            __syncthreads();
        }
    }

    // Epilogue: fold ||d||^2, store score
    float d2c[TN];
#pragma unroll
    for (int j = 0; j < TN; ++j) d2c[j] = g_d2[col0 + tx * TN + j];
#pragma unroll
    for (int i = 0; i < TM; ++i) {
        size_t base = (size_t)(row0 + ty * TM + i) * NPAD + col0 + tx * TN;
#pragma unroll
        for (int j = 0; j < TN; ++j)
            g_scores[base + j] = fmaf(-2.f, acc[i][j], d2c[j]);
    }
}

// ---------------------------------------------------------------------------
// Kernel 3: per-query exact top-10 + mode. One block (256 threads) per query.
//
// Phase 1: float4 streaming, per-thread sorted top-10 (insertion, strict <
//          keeps lowest index on ties within a thread).
// Phase 2: pack (score,idx) -> order-preserving u64 key (ties -> lower index),
//          then 8 levels of pairwise sorted-list merges (1 sync per level).
// ---------------------------------------------------------------------------
__device__ __forceinline__ unsigned long long pack_key(float v, int idx) {
    unsigned int b = __float_as_uint(v);
    b = (b & 0x80000000u) ? ~b : (b | 0x80000000u);   // monotone float -> uint
    return ((unsigned long long)b << 32) | (unsigned int)idx;
}

__global__ __launch_bounds__(256) void topk_mode_kernel(const int* __restrict__ t32,
                                                        float* __restrict__ out) {
    const int q   = blockIdx.x;
    const int tid = threadIdx.x;
    const float4* row4 = reinterpret_cast<const float4*>(g_scores + (size_t)q * NPAD);

    float val[10];
    int   idx[10];
#pragma unroll
    for (int i = 0; i < 10; ++i) { val[i] = FLT_MAX; idx[i] = 0x7fffffff; }

    // 50000/4 = 12500 float4s, strided by 256 threads (49 iterations)
    for (int it = 0; it < 49; ++it) {
        int v4 = tid + it * 256;
        if (v4 >= 12500) break;
        float4 v = row4[v4];
        int j0 = v4 * 4;
        float e[4] = {v.x, v.y, v.z, v.w};
#pragma unroll
        for (int c = 0; c < 4; ++c) {
            float f = e[c];
            if (f < val[9]) {
                int p = 9;
                while (p > 0 && f < val[p - 1]) {
                    val[p] = val[p - 1]; idx[p] = idx[p - 1]; --p;
                }
                val[p] = f; idx[p] = j0 + c;
            }
        }
    }

    // Pack sorted list into u64 keys (ascending)
    __shared__ unsigned long long slist[256][10];
#pragma unroll
    for (int i = 0; i < 10; ++i) slist[tid][i] = pack_key(val[i], idx[i]);
    __syncthreads();

    // Pairwise merge: 256 -> 1 sorted top-10 lists
    for (int L = 128; L >= 1; L >>= 1) {
        if (tid < L) {
            unsigned long long A[10];
#pragma unroll
            for (int i = 0; i < 10; ++i) A[i] = slist[tid][i];
            const unsigned long long* B = slist[tid + L];
            unsigned long long outm[10];
            int ia = 0, ib = 0;
#pragma unroll
            for (int i = 0; i < 10; ++i) {
                unsigned long long av = A[ia], bv = B[ib];
                if (av <= bv) { outm[i] = av; ++ia; }
                else          { outm[i] = bv; ++ib; }
            }
#pragma unroll
            for (int i = 0; i < 10; ++i) slist[tid][i] = outm[i];
        }
        __syncthreads();
    }

    if (tid == 0) {
        const int is64 = g_t_is_i64;
        int lab[10];
#pragma unroll
        for (int i = 0; i < 10; ++i) {
            int w = (int)(slist[0][i] & 0xffffffffu);
            lab[i] = is64 ? t32[2 * w] : t32[w];
        }
        int bestLab = 0x7fffffff, bestCnt = 0;
#pragma unroll
        for (int i = 0; i < 10; ++i) {
            int c = 0;
#pragma unroll
            for (int j2 = 0; j2 < 10; ++j2) c += (lab[j2] == lab[i]) ? 1 : 0;
            if (c > bestCnt || (c == bestCnt && lab[i] < bestLab)) { bestCnt = c; bestLab = lab[i]; }
        }
        out[q] = (float)bestLab;
    }
}

// ---------------------------------------------------------------------------
extern "C" void kernel_launch(void* const* d_in, const int* in_sizes, int n_in,
                              void* d_out, int out_size) {
    const float* X    = nullptr;
    const float* data = nullptr;
    const int*   t32  = nullptr;
    for (int i = 0; i < n_in; ++i) {
        if (in_sizes[i] == Q * D)            X    = (const float*)d_in[i];
        else if (in_sizes[i] == NDATA * D)   data = (const float*)d_in[i];
        else if (in_sizes[i] == NDATA)       t32  = (const int*)d_in[i];
    }
    float* out = (float*)d_out;
    (void)out_size;

    detect_dtype_kernel<<<1, 256>>>(t32);
    row_norms_kernel<<<(NDATA * 32 + 255) / 256, 256>>>(data);

    dim3 grid(NPAD / BN, Q / BM);   // 391 x 8
    score_gemm_kernel<<<grid, 256>>>(X, data);

    topk_mode_kernel<<<Q, 256>>>(t32, out);
}